// round 16
// baseline (speedup 1.0000x reference)
#include <cuda_runtime.h>
#include <cuda_bf16.h>
#include <cuda_fp16.h>
#include <math.h>

// Problem constants
#define VV   32000
#define EE   500
#define HH   500
#define DD1  800
#define DD2  100
#define CC   2
#define BB   64
#define TT   400
#define G4H  2000            // 4*H
#define MM   (BB*TT)         // 25600 rows of the big GEMMs
#define NREC_BLOCKS 125      // 125 * 4 units = 500
#define GSZH 16384           // halves per group slice (128 quads x 32b x 4) = 32KB
#define TMA_SPIN_CAP 65536   // bounded per-step wait (hang-proof)
#define PROBE_SPIN   16384   // bounded probe wait at init

// ---------------- scratch (device globals; no allocation allowed) ----------------
__device__ float  g_xz [(size_t)MM * G4H];             // 204.8 MB, reused for both layers
__device__ float  g_hs1[(size_t)MM * HH];              // 51.2 MB
__device__ __align__(128) __half g_hb0[2 * GSZH];      // [group][slice], fp16 h exchange
__device__ __align__(128) __half g_hb1[2 * GSZH];
__device__ float  g_d1 [BB * DD1];
__device__ float  g_d2 [BB * DD2];
// all-to-all flag barrier: one 128B line per (group, block); monotonic step counts
__device__ unsigned g_fl[2][NREC_BLOCKS * 32];
__device__ unsigned g_icnt[32];
__device__ unsigned g_isns[32];

// ---------------- packed f32x2 helpers ----------------
__device__ __forceinline__ unsigned long long pk2(float lo, float hi){
    unsigned long long r;
    asm("mov.b64 %0, {%1, %2};" : "=l"(r) : "f"(lo), "f"(hi));
    return r;
}
__device__ __forceinline__ unsigned long long dup2(float v){
    unsigned long long r;
    asm("mov.b64 %0, {%1, %1};" : "=l"(r) : "f"(v));
    return r;
}
__device__ __forceinline__ void fma2(unsigned long long &d,
                                     unsigned long long a,
                                     unsigned long long b){
    asm("fma.rn.f32x2 %0, %1, %2, %3;" : "=l"(d) : "l"(a), "l"(b), "l"(d));
}
__device__ __forceinline__ void unpk2(unsigned long long v, float &lo, float &hi){
    asm("mov.b64 {%0, %1}, %2;" : "=f"(lo), "=f"(hi) : "l"(v));
}

// ---------------- cp.async helpers (fallback staging path) ----------------
__device__ __forceinline__ void cp_async16(unsigned saddr, const void* gptr){
    asm volatile("cp.async.cg.shared.global [%0], [%1], 16;"
                 :: "r"(saddr), "l"(gptr) : "memory");
}
#define CP_COMMIT()  asm volatile("cp.async.commit_group;" ::: "memory")
#define CP_WAIT0()   asm volatile("cp.async.wait_group 0;" ::: "memory")

// =====================================================================
// SGEMM: C[M=25600, N=2000] = A[M,500] @ Bw[500,2000] + bias
// GATHER=1: A row m -> embed[X[b*T+t]] with m = t*64+b
// =====================================================================
template<int GATHER>
__global__ __launch_bounds__(256)
void sgemm_xz(const int* __restrict__ X, const float* __restrict__ A,
              const float* __restrict__ Bw, const float* __restrict__ bias,
              float* __restrict__ Cmat)
{
    __shared__ float As[8][128];
    __shared__ float Bs[8][128];

    const int tid = threadIdx.x;
    const int tx  = tid & 15;
    const int ty  = tid >> 4;
    const int m0  = blockIdx.y * 128;
    const int n0  = blockIdx.x * 128;

    const int ar  = tid >> 1;
    const int akq = (tid & 1) * 4;
    const float* arow_ptr;
    {
        int m = m0 + ar;
        if (GATHER){
            int t = m >> 6, b = m & 63;
            int tok = X[b * TT + t];
            arow_ptr = A + (size_t)tok * EE;
        } else {
            arow_ptr = A + (size_t)m * HH;
        }
    }
    const int bk = tid >> 5;
    const int bn = (tid & 31) * 4;

    unsigned long long acc[8][4];
    #pragma unroll
    for (int i = 0; i < 8; i++)
        #pragma unroll
        for (int j = 0; j < 4; j++) acc[i][j] = 0ULL;

    const float4 f40 = make_float4(0.f, 0.f, 0.f, 0.f);
    float4 aReg, bReg;
    {
        int k  = akq;
        aReg = (k < 500) ? *(const float4*)(arow_ptr + k) : f40;
        int kb = bk, n = n0 + bn;
        bReg = (kb < 500 && n < G4H) ? *(const float4*)(Bw + (size_t)kb * G4H + n) : f40;
    }

    const int KT = 63;
    for (int kt = 0; kt < KT; kt++){
        __syncthreads();
        As[akq+0][ar] = aReg.x; As[akq+1][ar] = aReg.y;
        As[akq+2][ar] = aReg.z; As[akq+3][ar] = aReg.w;
        *(float4*)(&Bs[bk][bn]) = bReg;
        __syncthreads();

        if (kt + 1 < KT){
            int k = (kt+1)*8 + akq;
            aReg = (k < 500) ? *(const float4*)(arow_ptr + k) : f40;
            int kb = (kt+1)*8 + bk, n = n0 + bn;
            bReg = (kb < 500 && n < G4H) ? *(const float4*)(Bw + (size_t)kb * G4H + n) : f40;
        }

        #pragma unroll
        for (int kk = 0; kk < 8; kk++){
            float4 a0 = *(const float4*)(&As[kk][ty*8]);
            float4 a1 = *(const float4*)(&As[kk][ty*8 + 4]);
            const unsigned long long* bp2 = (const unsigned long long*)(&Bs[kk][tx*8]);
            unsigned long long b0 = bp2[0], b1 = bp2[1], b2 = bp2[2], b3 = bp2[3];
            float av[8] = {a0.x,a0.y,a0.z,a0.w,a1.x,a1.y,a1.z,a1.w};
            #pragma unroll
            for (int i = 0; i < 8; i++){
                unsigned long long ad = dup2(av[i]);
                fma2(acc[i][0], ad, b0);
                fma2(acc[i][1], ad, b1);
                fma2(acc[i][2], ad, b2);
                fma2(acc[i][3], ad, b3);
            }
        }
    }

    const int nc = n0 + tx * 8;
    if (nc < G4H){
        float4 bb0 = *(const float4*)(bias + nc);
        float4 bb1 = *(const float4*)(bias + nc + 4);
        #pragma unroll
        for (int i = 0; i < 8; i++){
            int m = m0 + ty*8 + i;
            float o[8];
            unpk2(acc[i][0], o[0], o[1]);
            unpk2(acc[i][1], o[2], o[3]);
            unpk2(acc[i][2], o[4], o[5]);
            unpk2(acc[i][3], o[6], o[7]);
            float4 r0 = make_float4(o[0]+bb0.x, o[1]+bb0.y, o[2]+bb0.z, o[3]+bb0.w);
            float4 r1 = make_float4(o[4]+bb1.x, o[5]+bb1.y, o[6]+bb1.z, o[7]+bb1.w);
            float* cp = Cmat + (size_t)m * G4H + nc;
            *(float4*)(cp)     = r0;
            *(float4*)(cp + 4) = r1;
        }
    }
}

// =====================================================================
// Persistent LSTM recurrence, two batch-groups per SM, fp16 h exchange,
// all-to-all FLAG barrier (no atomics, no counter, no release hop):
//   arrive: lt0 st.release its own flag line with target step
//   detect: lt0 sweeps all 125 flags (pipelined relaxed loads) + acq_rel fence
// Staging primary: one cp.async.bulk (shared::cta dst, 32KB) per group per
// step, gated by an init-time probe (zombie-safe). Fallback: per-thread
// cp.async (16 ops/thread). Weights fp32 in SMEM; math fp32.
// =====================================================================
__global__ void lstm_rec(const float* __restrict__ xz, const float* __restrict__ Wh,
                         float* __restrict__ hs_out, int store_hs,
                         __half* __restrict__ hb0, __half* __restrict__ hb1)
{
    extern __shared__ char smem[];
    __half* hsm = (__half*)smem;                               // 65536 B (2 x 32KB)
    float*  wsm = (float*)(smem + 65536);                      // 32000 B
    unsigned long long* mbars = (unsigned long long*)(smem + 97536);  // 3 x 8B
    volatile unsigned* s_flag = (volatile unsigned*)(smem + 97560);   // [3]

    const int tid = threadIdx.x;
    const int g   = tid >> 7;          // batch group 0/1
    const int lt  = tid & 127;         // lane within group
    const int bl  = lt & 31;           // batch within group
    const int u   = (lt >> 5) & 3;     // unit within block slice
    const int u0  = blockIdx.x * 4;
    const int uu  = u0 + u;
    const int b   = g * 32 + bl;       // global batch

    const unsigned mbar_g  = (unsigned)__cvta_generic_to_shared(&mbars[g]);
    const unsigned mbar_pr = (unsigned)__cvta_generic_to_shared(&mbars[2]);
    const unsigned probe_d = (unsigned)__cvta_generic_to_shared(smem + 97584); // 16B scratch

    unsigned fbase = 0, isense = 0;
    if (lt == 0)
        asm volatile("ld.relaxed.gpu.global.u32 %0, [%1];"
                     : "=r"(fbase) : "l"(&g_fl[g][blockIdx.x * 32]) : "memory");
    if (tid == 0)
        asm volatile("ld.relaxed.gpu.global.u32 %0, [%1];" : "=r"(isense) : "l"(&g_isns[0]) : "memory");

    // init mbarriers (arrive count 1 = the expect_tx arrival)
    if (tid == 0){
        #pragma unroll
        for (int i = 0; i < 3; i++)
            asm volatile("mbarrier.init.shared.b64 [%0], %1;"
                         :: "r"((unsigned)__cvta_generic_to_shared(&mbars[i])), "r"(1u) : "memory");
    }

    // cache weight slice: wsm[k*16 + uw*4 + gate] = Wh[k*2000 + gate*500 + u0+uw]
    for (int idx = tid; idx < 500 * 16; idx += 256){
        int k = idx >> 4, r = idx & 15;
        int uw = r >> 2, gg = r & 3;
        wsm[idx] = Wh[(size_t)k * G4H + gg * HH + u0 + uw];
    }
    // zero both h buffers (fp16, incl. pad quads)
    {
        int gt = blockIdx.x * 256 + tid;
        uint4 z4 = make_uint4(0, 0, 0, 0);
        for (int i = gt; i < (2 * GSZH) / 8; i += NREC_BLOCKS * 256){
            ((uint4*)hb0)[i] = z4;
            ((uint4*)hb1)[i] = z4;
        }
    }
    __syncthreads();

    // ---- TMA PROBE (once, zombie-safe): 16B bulk copy into scratch ----
    if (tid == 0){
        asm volatile("fence.proxy.async;" ::: "memory");
        asm volatile("mbarrier.arrive.expect_tx.shared.b64 _, [%0], %1;"
                     :: "r"(mbar_pr), "r"(16u) : "memory");
        asm volatile("cp.async.bulk.shared::cta.global.mbarrier::complete_tx::bytes "
                     "[%0], [%1], %2, [%3];"
                     :: "r"(probe_d), "l"((const void*)hb0), "r"(16u), "r"(mbar_pr) : "memory");
        unsigned done = 0;
        int it = 0;
        do {
            asm volatile(
                "{\n\t.reg .pred p;\n\t"
                "mbarrier.try_wait.parity.acquire.cta.shared::cta.b64 p, [%1], %2;\n\t"
                "selp.b32 %0, 1, 0, p;\n\t}"
                : "=r"(done) : "r"(mbar_pr), "r"(0u) : "memory");
        } while (!done && ++it < PROBE_SPIN);
        s_flag[2] = done;
    }
    __syncthreads();
    bool use_tma = (s_flag[2] != 0);

    // init: full-grid barrier (atomic, one-time) so weights/zeros/mbarriers ready
    if (tid == 0){
        unsigned target = isense + 1u, old;
        asm volatile("atom.acq_rel.gpu.global.add.u32 %0, [%1], %2;"
                     : "=r"(old) : "l"(&g_icnt[0]), "r"(1u) : "memory");
        if (old == (unsigned)(NREC_BLOCKS - 1)){
            asm volatile("st.relaxed.gpu.global.u32 [%0], %1;" :: "l"(&g_icnt[0]), "r"(0u) : "memory");
            asm volatile("st.release.gpu.global.u32 [%0], %1;" :: "l"(&g_isns[0]), "r"(target) : "memory");
        } else {
            unsigned v;
            do {
                asm volatile("ld.acquire.gpu.global.u32 %0, [%1];" : "=r"(v) : "l"(&g_isns[0]) : "memory");
            } while ((int)(v - target) < 0);
        }
    }
    __syncthreads();

    __half* hsg = hsm + g * GSZH;
    const unsigned hsg_s = (unsigned)__cvta_generic_to_shared(hsg);
    float cst = 0.f;
    const int hoff = g * GSZH + (uu >> 2) * 128 + bl * 4 + (uu & 3);
    const float* xzb = xz + (size_t)b * G4H + uu;
    unsigned ph = 0;                    // mbarrier phase parity
    const unsigned* flg = &g_fl[g][0];  // this group's flag array
    unsigned* myflag = &g_fl[g][blockIdx.x * 32];

    for (int t = 0; t < TT; t++){
        const __half* hprev = ((t & 1) ? hb1 : hb0) + g * GSZH;
        __half*       hnext = ((t & 1) ? hb0 : hb1);

        // primary: ONE bulk copy (32KB) for this group's slice
        if (use_tma && lt == 0){
            asm volatile("fence.proxy.async;" ::: "memory");
            asm volatile("mbarrier.arrive.expect_tx.shared.b64 _, [%0], %1;"
                         :: "r"(mbar_g), "r"(32768u) : "memory");
            asm volatile("cp.async.bulk.shared::cta.global.mbarrier::complete_tx::bytes "
                         "[%0], [%1], %2, [%3];"
                         :: "r"(hsg_s), "l"((const void*)hprev), "r"(32768u), "r"(mbar_g) : "memory");
        }

        // xz loads (DRAM) fly during the transfer; added at the END (off chain)
        size_t mrow = (size_t)t * BB * G4H;
        float xi = __ldcs(xzb + mrow);
        float xj = __ldcs(xzb + mrow + 500);
        float xf = __ldcs(xzb + mrow + 1000);
        float xo = __ldcs(xzb + mrow + 1500);

        bool staged = false;
        if (use_tma){
            if (lt == 0){
                unsigned done = 0;
                int it = 0;
                do {
                    asm volatile(
                        "{\n\t.reg .pred p;\n\t"
                        "mbarrier.try_wait.parity.acquire.cta.shared::cta.b64 p, [%1], %2;\n\t"
                        "selp.b32 %0, 1, 0, p;\n\t}"
                        : "=r"(done) : "r"(mbar_g), "r"(ph) : "memory");
                } while (!done && ++it < TMA_SPIN_CAP);
                s_flag[g] = done;
            }
            asm volatile("bar.sync %0, 128;" :: "r"(3 + g) : "memory");
            if (s_flag[g]){
                ph ^= 1u;
                staged = true;
            } else {
                use_tma = false;
            }
        }
        if (!staged){
            #pragma unroll
            for (int i = 0; i < 16; i++){
                int idx = lt + i * 128;
                cp_async16(hsg_s + idx * 16, (const float4*)hprev + idx);
            }
            CP_COMMIT();
            CP_WAIT0();
            asm volatile("bar.sync %0, 128;" :: "r"(3 + g) : "memory");
        }

        unsigned long long aij = 0ULL, afo = 0ULL;
        #pragma unroll 5
        for (int q = 0; q < 125; q++){
            uint2 hraw = *(const uint2*)(hsg + q * 128 + bl * 4);   // 4 halves
            float2 f01 = __half22float2(*(const __half2*)&hraw.x);
            float2 f23 = __half22float2(*(const __half2*)&hraw.y);
            const float* wq = wsm + q * 64 + u * 4;
            ulonglong2 w0 = *(const ulonglong2*)(wq);
            ulonglong2 w1 = *(const ulonglong2*)(wq + 16);
            ulonglong2 w2 = *(const ulonglong2*)(wq + 32);
            ulonglong2 w3 = *(const ulonglong2*)(wq + 48);
            fma2(aij, dup2(f01.x), w0.x); fma2(afo, dup2(f01.x), w0.y);
            fma2(aij, dup2(f01.y), w1.x); fma2(afo, dup2(f01.y), w1.y);
            fma2(aij, dup2(f23.x), w2.x); fma2(afo, dup2(f23.x), w2.y);
            fma2(aij, dup2(f23.y), w3.x); fma2(afo, dup2(f23.y), w3.y);
        }

        float si, sj, sf, so;
        unpk2(aij, si, sj);
        unpk2(afo, sf, so);
        float zi = si + xi, zj = sj + xj, zf = sf + xf, zo = so + xo;

        float ig = 1.f / (1.f + expf(-zi));
        float fg = 1.f / (1.f + expf(-(zf + 1.f)));
        float og = 1.f / (1.f + expf(-zo));
        float jt = tanhf(zj);
        cst = fg * cst + ig * jt;
        float hv = og * tanhf(cst);

        unsigned short hv16 = __half_as_ushort(__float2half(hv));
        asm volatile("st.global.cg.u16 [%0], %1;"
                     :: "l"(hnext + hoff), "h"(hv16) : "memory");
        if (store_hs)
            hs_out[(size_t)(t * BB + b) * HH + uu] = hv;   // fp32 for SGEMM2

        // ---- all-to-all flag barrier ----
        asm volatile("bar.sync %0, 128;" :: "r"(3 + g) : "memory");
        if (lt == 0){
            unsigned target = fbase + (unsigned)t + 1u;
            asm volatile("st.release.gpu.global.u32 [%0], %1;"
                         :: "l"(myflag), "r"(target) : "memory");
            bool all;
            do {
                all = true;
                #pragma unroll 25
                for (int i = 0; i < NREC_BLOCKS; i++){
                    unsigned v;
                    asm volatile("ld.relaxed.gpu.global.u32 %0, [%1];"
                                 : "=r"(v) : "l"(flg + i * 32) : "memory");
                    all &= ((int)(v - target) >= 0);
                }
            } while (!all);
            asm volatile("fence.acq_rel.gpu;" ::: "memory");
        }
        asm volatile("bar.sync %0, 128;" :: "r"(3 + g) : "memory");
    }
}

// =====================================================================
// Small dense layers. transposed_in: in = fp16 grouped quad-packed h layout.
// =====================================================================
__global__ void dense_kernel(const float* __restrict__ in, const float* __restrict__ W,
                             const float* __restrict__ bias, float* __restrict__ out,
                             int Kdim, int Ndim, int transposed_in, int do_relu)
{
    int gidx = blockIdx.x * blockDim.x + threadIdx.x;
    if (gidx >= BB * Ndim) return;
    int bv = gidx / Ndim;
    int j  = gidx - bv * Ndim;
    float acc = bias[j];
    if (transposed_in){
        const __half* inh = (const __half*)in;
        int base = (bv >> 5) * GSZH + (bv & 31) * 4;
        #pragma unroll 8
        for (int k = 0; k < Kdim; k++)
            acc += __half2float(inh[base + (k >> 2) * 128 + (k & 3)]) * W[k * Ndim + j];
    } else {
        #pragma unroll 8
        for (int k = 0; k < Kdim; k++)
            acc += in[bv * Kdim + k] * W[k * Ndim + j];
    }
    out[gidx] = do_relu ? fmaxf(acc, 0.f) : acc;
}

// =====================================================================
// Launch
// =====================================================================
#define REC_SMEM 97664   // 65536 h-stage + 32000 weights + mbars/flags/probe

extern "C" void kernel_launch(void* const* d_in, const int* in_sizes, int n_in,
                              void* d_out, int out_size)
{
    const int*   X     = (const int*)  d_in[0];
    const float* embed = (const float*)d_in[1];
    const float* k1    = (const float*)d_in[2];
    const float* b1    = (const float*)d_in[3];
    const float* k2    = (const float*)d_in[4];
    const float* b2    = (const float*)d_in[5];
    const float* w1    = (const float*)d_in[6];
    const float* bw1   = (const float*)d_in[7];
    const float* w2    = (const float*)d_in[8];
    const float* bw2   = (const float*)d_in[9];
    const float* wp    = (const float*)d_in[10];
    const float* bp    = (const float*)d_in[11];
    float* out = (float*)d_out;

    float *xz, *hs1, *d1, *d2;
    __half *hb0, *hb1;
    cudaGetSymbolAddress((void**)&xz,  g_xz);
    cudaGetSymbolAddress((void**)&hs1, g_hs1);
    cudaGetSymbolAddress((void**)&hb0, g_hb0);
    cudaGetSymbolAddress((void**)&hb1, g_hb1);
    cudaGetSymbolAddress((void**)&d1,  g_d1);
    cudaGetSymbolAddress((void**)&d2,  g_d2);

    cudaFuncSetAttribute(lstm_rec, cudaFuncAttributeMaxDynamicSharedMemorySize, REC_SMEM);

    dim3 ggrid(16, 200);   // N tiles x M tiles

    // layer 1: xz1 = embed[X] @ k1[:E] + b1 ; then recurrence (stores hs1 fp32)
    sgemm_xz<1><<<ggrid, 256>>>(X, embed, k1, b1, xz);
    lstm_rec<<<NREC_BLOCKS, 256, REC_SMEM>>>(xz, k1 + (size_t)EE * G4H,
                                             hs1, 1, hb0, hb1);

    // layer 2: xz2 = hs1 @ k2[:H] + b2 ; recurrence (final h only)
    sgemm_xz<0><<<ggrid, 256>>>(nullptr, hs1, k2, b2, xz);
    lstm_rec<<<NREC_BLOCKS, 256, REC_SMEM>>>(xz, k2 + (size_t)HH * G4H,
                                             nullptr, 0, hb0, hb1);

    // head: T=400 even -> final h (fp16) in hb0 (written at t=399)
    dense_kernel<<<(BB*DD1 + 255)/256, 256>>>((const float*)hb0, w1, bw1, d1, HH,  DD1, 1, 1);
    dense_kernel<<<(BB*DD2 + 255)/256, 256>>>(d1,  w2, bw2, d2, DD1, DD2, 0, 1);
    dense_kernel<<<1, BB*CC>>>(d2, wp, bp, out, DD2, CC, 0, 0);
}

// round 17
// speedup vs baseline: 1.1202x; 1.1202x over previous
#include <cuda_runtime.h>
#include <cuda_bf16.h>
#include <cuda_fp16.h>
#include <math.h>

// Problem constants
#define VV   32000
#define EE   500
#define HH   500
#define DD1  800
#define DD2  100
#define CC   2
#define BB   64
#define TT   400
#define G4H  2000            // 4*H
#define MM   (BB*TT)         // 25600 rows (m = t*64 + b)
#define NREC_BLOCKS 125      // 125 * 4 units = 500
#define GSZH 16384           // halves per group slice (128 quads x 32b x 4) = 32KB
#define TMA_SPIN_CAP 65536   // bounded per-step wait (hang-proof)
#define PROBE_SPIN   16384   // bounded probe wait at init

// ---------------- scratch (device globals; no allocation allowed) ----------------
// xz and hs1 are stored TRANSPOSED: [col][m], m = t*64+b. This makes the
// recurrence's per-step loads/stores fully coalesced (1 line per warp access
// instead of 32), removing the scattered-DRAM straggler jitter that the
// 800 grid barriers amplify (max over 125 blocks each step).
__device__ float  g_xz [(size_t)G4H * MM];             // 204.8 MB, transposed
__device__ float  g_hs1[(size_t)HH * MM];              // 51.2 MB, transposed
__device__ __align__(128) __half g_hb0[2 * GSZH];      // [group][slice], fp16 h exchange
__device__ __align__(128) __half g_hb1[2 * GSZH];
__device__ float  g_d1 [BB * DD1];
__device__ float  g_d2 [BB * DD2];
// barrier state: counter and sense on separate 128B lines, per group
__device__ unsigned g_gcnt[2][32];
__device__ unsigned g_gsns[2][32];
__device__ unsigned g_icnt[32];
__device__ unsigned g_isns[32];

// ---------------- packed f32x2 helpers ----------------
__device__ __forceinline__ unsigned long long dup2(float v){
    unsigned long long r;
    asm("mov.b64 %0, {%1, %1};" : "=l"(r) : "f"(v));
    return r;
}
__device__ __forceinline__ void fma2(unsigned long long &d,
                                     unsigned long long a,
                                     unsigned long long b){
    asm("fma.rn.f32x2 %0, %1, %2, %3;" : "=l"(d) : "l"(a), "l"(b), "l"(d));
}
__device__ __forceinline__ void unpk2(unsigned long long v, float &lo, float &hi){
    asm("mov.b64 {%0, %1}, %2;" : "=f"(lo), "=f"(hi) : "l"(v));
}

// ---------------- cp.async helpers (fallback staging path) ----------------
__device__ __forceinline__ void cp_async16(unsigned saddr, const void* gptr){
    asm volatile("cp.async.cg.shared.global [%0], [%1], 16;"
                 :: "r"(saddr), "l"(gptr) : "memory");
}
#define CP_COMMIT()  asm volatile("cp.async.commit_group;" ::: "memory")
#define CP_WAIT0()   asm volatile("cp.async.wait_group 0;" ::: "memory")

// =====================================================================
// SGEMM producing TRANSPOSED output: C_T[n][m] = sum_k A[m][k]*Bw[k][n] + bias[n]
// GATHER=1: A row m -> embed[X[b*T+t]] with m = t*64+b (row-major embed)
// GATHER=0: A is hs1_T[k][m] (transposed), loaded coalesced like the B tile.
// 128(m) x 128(n) block tile, BK=8, 256 threads, 8x8 per-thread tile, f32x2.
// =====================================================================
template<int GATHER>
__global__ __launch_bounds__(256)
void sgemm_xz(const int* __restrict__ X, const float* __restrict__ A,
              const float* __restrict__ Bw, const float* __restrict__ bias,
              float* __restrict__ Cmat)
{
    __shared__ float As[8][128];
    __shared__ float Bs[8][128];

    const int tid = threadIdx.x;
    const int tx  = tid & 15;
    const int ty  = tid >> 4;
    const int m0  = blockIdx.y * 128;
    const int n0  = blockIdx.x * 128;

    // gather-mode A loader indices
    const int ar  = tid >> 1;
    const int akq = (tid & 1) * 4;
    const float* arow_ptr = nullptr;
    if (GATHER){
        int m = m0 + ar;
        int t = m >> 6, b = m & 63;
        int tok = X[b * TT + t];
        arow_ptr = A + (size_t)tok * EE;
    }
    // B loader (and transposed-A loader) indices
    const int bk = tid >> 5;
    const int bn = (tid & 31) * 4;

    unsigned long long acc[8][4];
    #pragma unroll
    for (int i = 0; i < 8; i++)
        #pragma unroll
        for (int j = 0; j < 4; j++) acc[i][j] = 0ULL;

    const float4 f40 = make_float4(0.f, 0.f, 0.f, 0.f);
    float4 aReg, bReg;
    {
        if (GATHER){
            int k = akq;
            aReg = (k < 500) ? *(const float4*)(arow_ptr + k) : f40;
        } else {
            int kb = bk;
            aReg = (kb < 500) ? *(const float4*)(A + (size_t)kb * MM + m0 + bn) : f40;
        }
        int kb = bk, n = n0 + bn;
        bReg = (kb < 500 && n < G4H) ? *(const float4*)(Bw + (size_t)kb * G4H + n) : f40;
    }

    const int KT = 63;
    for (int kt = 0; kt < KT; kt++){
        __syncthreads();
        if (GATHER){
            As[akq+0][ar] = aReg.x; As[akq+1][ar] = aReg.y;
            As[akq+2][ar] = aReg.z; As[akq+3][ar] = aReg.w;
        } else {
            *(float4*)(&As[bk][bn]) = aReg;
        }
        *(float4*)(&Bs[bk][bn]) = bReg;
        __syncthreads();

        if (kt + 1 < KT){
            if (GATHER){
                int k = (kt+1)*8 + akq;
                aReg = (k < 500) ? *(const float4*)(arow_ptr + k) : f40;
            } else {
                int kb = (kt+1)*8 + bk;
                aReg = (kb < 500) ? *(const float4*)(A + (size_t)kb * MM + m0 + bn) : f40;
            }
            int kb = (kt+1)*8 + bk, n = n0 + bn;
            bReg = (kb < 500 && n < G4H) ? *(const float4*)(Bw + (size_t)kb * G4H + n) : f40;
        }

        #pragma unroll
        for (int kk = 0; kk < 8; kk++){
            float4 a0 = *(const float4*)(&As[kk][ty*8]);
            float4 a1 = *(const float4*)(&As[kk][ty*8 + 4]);
            const unsigned long long* bp2 = (const unsigned long long*)(&Bs[kk][tx*8]);
            unsigned long long b0 = bp2[0], b1 = bp2[1], b2 = bp2[2], b3 = bp2[3];
            float av[8] = {a0.x,a0.y,a0.z,a0.w,a1.x,a1.y,a1.z,a1.w};
            #pragma unroll
            for (int i = 0; i < 8; i++){
                unsigned long long ad = dup2(av[i]);
                fma2(acc[i][0], ad, b0);
                fma2(acc[i][1], ad, b1);
                fma2(acc[i][2], ad, b2);
                fma2(acc[i][3], ad, b3);
            }
        }
    }

    // epilogue: +bias, store TRANSPOSED C_T[n][m]
    const int nc = n0 + tx * 8;
    if (nc < G4H){
        const int mrow = m0 + ty * 8;
        #pragma unroll
        for (int jn = 0; jn < 8; jn++){
            int n = nc + jn;
            float bb = bias[n];
            float o[8];
            #pragma unroll
            for (int i = 0; i < 8; i++){
                float lo, hi;
                unpk2(acc[i][jn >> 1], lo, hi);
                o[i] = (jn & 1) ? hi : lo;
            }
            float4 r0 = make_float4(o[0]+bb, o[1]+bb, o[2]+bb, o[3]+bb);
            float4 r1 = make_float4(o[4]+bb, o[5]+bb, o[6]+bb, o[7]+bb);
            float* cp = Cmat + (size_t)n * MM + mrow;
            *(float4*)(cp)     = r0;
            *(float4*)(cp + 4) = r1;
        }
    }
}

// =====================================================================
// Persistent LSTM recurrence, two batch-groups per SM, fp16 h exchange,
// per-group atomic grid barrier (best-measured variant, R14).
// xz is TRANSPOSED [col][m]: the 4 per-step gate loads are coalesced
// (1 line per warp instead of 32) — removes the scattered-DRAM straggler
// jitter the barrier amplifies. hs1 output likewise transposed.
// Staging primary: one cp.async.bulk (shared::cta dst, 32KB) per group per
// step, gated by an init-time probe (zombie-safe). Fallback: per-thread
// cp.async. Weights fp32 in SMEM; math fp32.
// =====================================================================
__global__ void lstm_rec(const float* __restrict__ xz, const float* __restrict__ Wh,
                         float* __restrict__ hs_out, int store_hs,
                         __half* __restrict__ hb0, __half* __restrict__ hb1)
{
    extern __shared__ char smem[];
    __half* hsm = (__half*)smem;                               // 65536 B (2 x 32KB)
    float*  wsm = (float*)(smem + 65536);                      // 32000 B
    unsigned long long* mbars = (unsigned long long*)(smem + 97536);  // 3 x 8B
    volatile unsigned* s_flag = (volatile unsigned*)(smem + 97560);   // [3]

    const int tid = threadIdx.x;
    const int g   = tid >> 7;          // batch group 0/1
    const int lt  = tid & 127;         // lane within group
    const int bl  = lt & 31;           // batch within group
    const int u   = (lt >> 5) & 3;     // unit within block slice
    const int u0  = blockIdx.x * 4;
    const int uu  = u0 + u;
    const int b   = g * 32 + bl;       // global batch

    const unsigned mbar_g  = (unsigned)__cvta_generic_to_shared(&mbars[g]);
    const unsigned mbar_pr = (unsigned)__cvta_generic_to_shared(&mbars[2]);
    const unsigned probe_d = (unsigned)__cvta_generic_to_shared(smem + 97584); // 16B scratch

    unsigned gsense = 0, isense = 0;
    if (lt == 0)
        asm volatile("ld.relaxed.gpu.global.u32 %0, [%1];" : "=r"(gsense) : "l"(&g_gsns[g][0]) : "memory");
    if (tid == 0)
        asm volatile("ld.relaxed.gpu.global.u32 %0, [%1];" : "=r"(isense) : "l"(&g_isns[0]) : "memory");

    // init mbarriers (arrive count 1 = the expect_tx arrival)
    if (tid == 0){
        #pragma unroll
        for (int i = 0; i < 3; i++)
            asm volatile("mbarrier.init.shared.b64 [%0], %1;"
                         :: "r"((unsigned)__cvta_generic_to_shared(&mbars[i])), "r"(1u) : "memory");
    }

    // cache weight slice: wsm[k*16 + uw*4 + gate] = Wh[k*2000 + gate*500 + u0+uw]
    for (int idx = tid; idx < 500 * 16; idx += 256){
        int k = idx >> 4, r = idx & 15;
        int uw = r >> 2, gg = r & 3;
        wsm[idx] = Wh[(size_t)k * G4H + gg * HH + u0 + uw];
    }
    // zero both h buffers (fp16, incl. pad quads)
    {
        int gt = blockIdx.x * 256 + tid;
        uint4 z4 = make_uint4(0, 0, 0, 0);
        for (int i = gt; i < (2 * GSZH) / 8; i += NREC_BLOCKS * 256){
            ((uint4*)hb0)[i] = z4;
            ((uint4*)hb1)[i] = z4;
        }
    }
    __syncthreads();

    // ---- TMA PROBE (once, zombie-safe): 16B bulk copy into scratch ----
    if (tid == 0){
        asm volatile("fence.proxy.async;" ::: "memory");
        asm volatile("mbarrier.arrive.expect_tx.shared.b64 _, [%0], %1;"
                     :: "r"(mbar_pr), "r"(16u) : "memory");
        asm volatile("cp.async.bulk.shared::cta.global.mbarrier::complete_tx::bytes "
                     "[%0], [%1], %2, [%3];"
                     :: "r"(probe_d), "l"((const void*)hb0), "r"(16u), "r"(mbar_pr) : "memory");
        unsigned done = 0;
        int it = 0;
        do {
            asm volatile(
                "{\n\t.reg .pred p;\n\t"
                "mbarrier.try_wait.parity.acquire.cta.shared::cta.b64 p, [%1], %2;\n\t"
                "selp.b32 %0, 1, 0, p;\n\t}"
                : "=r"(done) : "r"(mbar_pr), "r"(0u) : "memory");
        } while (!done && ++it < PROBE_SPIN);
        s_flag[2] = done;
    }
    __syncthreads();
    bool use_tma = (s_flag[2] != 0);

    // init: full-grid barrier so weights/zeros/mbarriers are ready everywhere
    if (tid == 0){
        unsigned target = isense + 1u, old;
        asm volatile("atom.acq_rel.gpu.global.add.u32 %0, [%1], %2;"
                     : "=r"(old) : "l"(&g_icnt[0]), "r"(1u) : "memory");
        if (old == (unsigned)(NREC_BLOCKS - 1)){
            asm volatile("st.relaxed.gpu.global.u32 [%0], %1;" :: "l"(&g_icnt[0]), "r"(0u) : "memory");
            asm volatile("st.release.gpu.global.u32 [%0], %1;" :: "l"(&g_isns[0]), "r"(target) : "memory");
        } else {
            unsigned v;
            do {
                asm volatile("ld.acquire.gpu.global.u32 %0, [%1];" : "=r"(v) : "l"(&g_isns[0]) : "memory");
            } while ((int)(v - target) < 0);
        }
    }
    __syncthreads();

    __half* hsg = hsm + g * GSZH;
    const unsigned hsg_s = (unsigned)__cvta_generic_to_shared(hsg);
    float cst = 0.f;
    const int hoff = g * GSZH + (uu >> 2) * 128 + bl * 4 + (uu & 3);
    // transposed xz base for this (unit, batch): col = gate*500 + uu, m = t*64+b
    const float* xzu = xz + (size_t)uu * MM + b;
    float* hsu = hs_out ? (hs_out + (size_t)uu * MM + b) : nullptr;
    unsigned ph = 0;                    // mbarrier phase parity

    for (int t = 0; t < TT; t++){
        const __half* hprev = ((t & 1) ? hb1 : hb0) + g * GSZH;
        __half*       hnext = ((t & 1) ? hb0 : hb1);

        // primary: ONE bulk copy (32KB) for this group's slice
        if (use_tma && lt == 0){
            asm volatile("fence.proxy.async;" ::: "memory");
            asm volatile("mbarrier.arrive.expect_tx.shared.b64 _, [%0], %1;"
                         :: "r"(mbar_g), "r"(32768u) : "memory");
            asm volatile("cp.async.bulk.shared::cta.global.mbarrier::complete_tx::bytes "
                         "[%0], [%1], %2, [%3];"
                         :: "r"(hsg_s), "l"((const void*)hprev), "r"(32768u), "r"(mbar_g) : "memory");
        }

        // coalesced xz loads (1 line per warp each); consumed after the MAC chain
        size_t tcol = (size_t)t * 64;
        float xi = __ldcs(xzu + tcol);
        float xj = __ldcs(xzu + (size_t)500  * MM + tcol);
        float xf = __ldcs(xzu + (size_t)1000 * MM + tcol);
        float xo = __ldcs(xzu + (size_t)1500 * MM + tcol);

        bool staged = false;
        if (use_tma){
            if (lt == 0){
                unsigned done = 0;
                int it = 0;
                do {
                    asm volatile(
                        "{\n\t.reg .pred p;\n\t"
                        "mbarrier.try_wait.parity.acquire.cta.shared::cta.b64 p, [%1], %2;\n\t"
                        "selp.b32 %0, 1, 0, p;\n\t}"
                        : "=r"(done) : "r"(mbar_g), "r"(ph) : "memory");
                } while (!done && ++it < TMA_SPIN_CAP);
                s_flag[g] = done;
            }
            asm volatile("bar.sync %0, 128;" :: "r"(3 + g) : "memory");
            if (s_flag[g]){
                ph ^= 1u;
                staged = true;
            } else {
                use_tma = false;
            }
        }
        if (!staged){
            #pragma unroll
            for (int i = 0; i < 16; i++){
                int idx = lt + i * 128;
                cp_async16(hsg_s + idx * 16, (const float4*)hprev + idx);
            }
            CP_COMMIT();
            CP_WAIT0();
            asm volatile("bar.sync %0, 128;" :: "r"(3 + g) : "memory");
        }

        unsigned long long aij = 0ULL, afo = 0ULL;
        #pragma unroll 5
        for (int q = 0; q < 125; q++){
            uint2 hraw = *(const uint2*)(hsg + q * 128 + bl * 4);   // 4 halves
            float2 f01 = __half22float2(*(const __half2*)&hraw.x);
            float2 f23 = __half22float2(*(const __half2*)&hraw.y);
            const float* wq = wsm + q * 64 + u * 4;
            ulonglong2 w0 = *(const ulonglong2*)(wq);
            ulonglong2 w1 = *(const ulonglong2*)(wq + 16);
            ulonglong2 w2 = *(const ulonglong2*)(wq + 32);
            ulonglong2 w3 = *(const ulonglong2*)(wq + 48);
            fma2(aij, dup2(f01.x), w0.x); fma2(afo, dup2(f01.x), w0.y);
            fma2(aij, dup2(f01.y), w1.x); fma2(afo, dup2(f01.y), w1.y);
            fma2(aij, dup2(f23.x), w2.x); fma2(afo, dup2(f23.x), w2.y);
            fma2(aij, dup2(f23.y), w3.x); fma2(afo, dup2(f23.y), w3.y);
        }

        float si, sj, sf, so;
        unpk2(aij, si, sj);
        unpk2(afo, sf, so);
        float zi = si + xi, zj = sj + xj, zf = sf + xf, zo = so + xo;

        float ig = 1.f / (1.f + expf(-zi));
        float fg = 1.f / (1.f + expf(-(zf + 1.f)));
        float og = 1.f / (1.f + expf(-zo));
        float jt = tanhf(zj);
        cst = fg * cst + ig * jt;
        float hv = og * tanhf(cst);

        unsigned short hv16 = __half_as_ushort(__float2half(hv));
        asm volatile("st.global.cg.u16 [%0], %1;"
                     :: "l"(hnext + hoff), "h"(hv16) : "memory");
        if (store_hs)
            hsu[tcol] = hv;             // transposed, coalesced

        // per-group atomic grid barrier (R14, best measured)
        asm volatile("bar.sync %0, 128;" :: "r"(3 + g) : "memory");
        if (lt == 0){
            unsigned target = gsense + 1u;
            unsigned old;
            asm volatile("atom.acq_rel.gpu.global.add.u32 %0, [%1], %2;"
                         : "=r"(old) : "l"(&g_gcnt[g][0]), "r"(1u) : "memory");
            if (old == (unsigned)(NREC_BLOCKS - 1)){
                asm volatile("st.relaxed.gpu.global.u32 [%0], %1;"
                             :: "l"(&g_gcnt[g][0]), "r"(0u) : "memory");
                asm volatile("st.release.gpu.global.u32 [%0], %1;"
                             :: "l"(&g_gsns[g][0]), "r"(target) : "memory");
            } else {
                unsigned v;
                do {
                    asm volatile("ld.acquire.gpu.global.u32 %0, [%1];"
                                 : "=r"(v) : "l"(&g_gsns[g][0]) : "memory");
                } while ((int)(v - target) < 0);
            }
            gsense = target;
        }
        asm volatile("bar.sync %0, 128;" :: "r"(3 + g) : "memory");
    }
}

// =====================================================================
// Small dense layers. transposed_in: in = fp16 grouped quad-packed h layout.
// =====================================================================
__global__ void dense_kernel(const float* __restrict__ in, const float* __restrict__ W,
                             const float* __restrict__ bias, float* __restrict__ out,
                             int Kdim, int Ndim, int transposed_in, int do_relu)
{
    int gidx = blockIdx.x * blockDim.x + threadIdx.x;
    if (gidx >= BB * Ndim) return;
    int bv = gidx / Ndim;
    int j  = gidx - bv * Ndim;
    float acc = bias[j];
    if (transposed_in){
        const __half* inh = (const __half*)in;
        int base = (bv >> 5) * GSZH + (bv & 31) * 4;
        #pragma unroll 8
        for (int k = 0; k < Kdim; k++)
            acc += __half2float(inh[base + (k >> 2) * 128 + (k & 3)]) * W[k * Ndim + j];
    } else {
        #pragma unroll 8
        for (int k = 0; k < Kdim; k++)
            acc += in[bv * Kdim + k] * W[k * Ndim + j];
    }
    out[gidx] = do_relu ? fmaxf(acc, 0.f) : acc;
}

// =====================================================================
// Launch
// =====================================================================
#define REC_SMEM 97664   // 65536 h-stage + 32000 weights + mbars/flags/probe

extern "C" void kernel_launch(void* const* d_in, const int* in_sizes, int n_in,
                              void* d_out, int out_size)
{
    const int*   X     = (const int*)  d_in[0];
    const float* embed = (const float*)d_in[1];
    const float* k1    = (const float*)d_in[2];
    const float* b1    = (const float*)d_in[3];
    const float* k2    = (const float*)d_in[4];
    const float* b2    = (const float*)d_in[5];
    const float* w1    = (const float*)d_in[6];
    const float* bw1   = (const float*)d_in[7];
    const float* w2    = (const float*)d_in[8];
    const float* bw2   = (const float*)d_in[9];
    const float* wp    = (const float*)d_in[10];
    const float* bp    = (const float*)d_in[11];
    float* out = (float*)d_out;

    float *xz, *hs1, *d1, *d2;
    __half *hb0, *hb1;
    cudaGetSymbolAddress((void**)&xz,  g_xz);
    cudaGetSymbolAddress((void**)&hs1, g_hs1);
    cudaGetSymbolAddress((void**)&hb0, g_hb0);
    cudaGetSymbolAddress((void**)&hb1, g_hb1);
    cudaGetSymbolAddress((void**)&d1,  g_d1);
    cudaGetSymbolAddress((void**)&d2,  g_d2);

    cudaFuncSetAttribute(lstm_rec, cudaFuncAttributeMaxDynamicSharedMemorySize, REC_SMEM);

    dim3 ggrid(16, 200);   // N tiles x M tiles

    // layer 1: xz1_T = (embed[X] @ k1[:E] + b1)^T ; then recurrence (stores hs1_T)
    sgemm_xz<1><<<ggrid, 256>>>(X, embed, k1, b1, xz);
    lstm_rec<<<NREC_BLOCKS, 256, REC_SMEM>>>(xz, k1 + (size_t)EE * G4H,
                                             hs1, 1, hb0, hb1);

    // layer 2: xz2_T = (hs1 @ k2[:H] + b2)^T ; recurrence (final h only)
    sgemm_xz<0><<<ggrid, 256>>>(nullptr, hs1, k2, b2, xz);
    lstm_rec<<<NREC_BLOCKS, 256, REC_SMEM>>>(xz, k2 + (size_t)HH * G4H,
                                             nullptr, 0, hb0, hb1);

    // head: T=400 even -> final h (fp16) in hb0 (written at t=399)
    dense_kernel<<<(BB*DD1 + 255)/256, 256>>>((const float*)hb0, w1, bw1, d1, HH,  DD1, 1, 1);
    dense_kernel<<<(BB*DD2 + 255)/256, 256>>>(d1,  w2, bw2, d2, DD1, DD2, 0, 1);
    dense_kernel<<<1, BB*CC>>>(d2, wp, bp, out, DD2, CC, 0, 0);
}